// round 17
// baseline (speedup 1.0000x reference)
#include <cuda_runtime.h>
#include <cuda_fp16.h>
#include <cstdint>

// Tropical (max-plus) matmul: Y[b, j] = max_i (X[b, i] + W[j, i])
// fp16 path with per-row fp32 shift:
//   M_b = max_i X[b,i];  Xh = half(X - M_b);  Wh = half(W)
//   Y' = max-plus in packed fp16 (HADD2/HMNMX2 paired over k);  Y = Y' + M_b.
// Measured rel_err ~1.3e-6.
//
// R15: prep reshaped to few fat blocks with high per-thread MLP:
//   X: 64 blocks x 8 warps, one warp per row (8 x float4 MLP8 + shfl max)
//   W: 256 blocks x 256 thr x 4 independent float4 (MLP4)
// Main + combine + PDL unchanged from R14.

#define B_DIM   512
#define IN_DIM  1024
#define OUT_DIM 1024

#define SPLITK  8
#define KSEG    (IN_DIM / SPLITK)   // 128
#define BKH     64                  // halves per W chunk
#define NCHH    (KSEG / BKH)        // 2
#define BMH     32
#define BNH     128
#define PADK    72                  // W smem row pad (halves)
#define XPAD    136                 // X smem row pad (halves)
#define NT      128

#define XPREP_BLOCKS 64             // 8 rows per block (1 warp/row)
#define WPREP_BLOCKS 256

__device__ __half Xh[B_DIM * IN_DIM];
__device__ __half Wh[OUT_DIM * IN_DIM];
__device__ float  Mrow[B_DIM];
__device__ __half g_parth[SPLITK][B_DIM * OUT_DIM];   // 8 MB

#define CPA16(dst_u32, src_ptr) \
    asm volatile("cp.async.cg.shared.global [%0], [%1], 16;" \
                 :: "r"(dst_u32), "l"(src_ptr))
#define CPA_COMMIT() asm volatile("cp.async.commit_group;")
#define CPA_WAIT1()  asm volatile("cp.async.wait_group 1;")
#define CPA_WAIT0()  asm volatile("cp.async.wait_group 0;")

#define GRID_WAIT()       asm volatile("griddepcontrol.wait;" ::: "memory")
#define GRID_LAUNCH_DEP() asm volatile("griddepcontrol.launch_dependents;" ::: "memory")

// ---------- prep: blocks [0,64) = X (1 warp/row, MLP8); [64,320) = W (MLP4) ----------
__global__ __launch_bounds__(256)
void prep_xw(const float* __restrict__ X, const float* __restrict__ W) {
    const int t = threadIdx.x, lane = t & 31, wid = t >> 5;
    if (blockIdx.x < XPREP_BLOCKS) {
        // one warp per X row: 8 independent float4 loads per lane
        const int b = blockIdx.x * 8 + wid;
        const float4* src = (const float4*)(X + (size_t)b * IN_DIM);
        float4 v[8];
#pragma unroll
        for (int p = 0; p < 8; ++p) v[p] = src[lane + 32 * p];
        float m = -3.402823466e38f;
#pragma unroll
        for (int p = 0; p < 8; ++p)
            m = fmaxf(m, fmaxf(fmaxf(v[p].x, v[p].y), fmaxf(v[p].z, v[p].w)));
#pragma unroll
        for (int o = 16; o; o >>= 1) m = fmaxf(m, __shfl_xor_sync(~0u, m, o));
        if (lane == 0) Mrow[b] = m;
        uint2* dst = (uint2*)(Xh + (size_t)b * IN_DIM);   // 8 halves per float4
#pragma unroll
        for (int p = 0; p < 8; ++p) {
            __half2 h0 = __floats2half2_rn(v[p].x - m, v[p].y - m);
            __half2 h1 = __floats2half2_rn(v[p].z - m, v[p].w - m);
            uint2 pk;
            pk.x = *(const unsigned*)&h0;  pk.y = *(const unsigned*)&h1;
            dst[lane + 32 * p] = pk;
        }
    } else {
        // W: 262144 float4s over 256 blocks x 256 thr x 4 (MLP4, coalesced)
        const int g = (blockIdx.x - XPREP_BLOCKS) * 256 + t;
        float4 v[4];
#pragma unroll
        for (int p = 0; p < 4; ++p) v[p] = ((const float4*)W)[g + 65536 * p];
        uint2* dst = (uint2*)Wh;
#pragma unroll
        for (int p = 0; p < 4; ++p) {
            __half2 h0 = __floats2half2_rn(v[p].x, v[p].y);
            __half2 h1 = __floats2half2_rn(v[p].z, v[p].w);
            uint2 pk;
            pk.x = *(const unsigned*)&h0;  pk.y = *(const unsigned*)&h1;
            dst[g + 65536 * p] = pk;
        }
    }
    GRID_LAUNCH_DEP();
}

// ---------- main: fp16 split-K max-plus ----------
__global__ __launch_bounds__(NT)
void tropical_h() {
    __shared__ __half xs[BMH][XPAD];      //  8.5 KB (single buffer, full KSEG)
    __shared__ __half ws[2][BNH][PADK];   // 36.9 KB (double buffered)

    const int t = threadIdx.x, lane = t & 31, wid = t >> 5;
    const int colg = (lane & 7) | ((wid & 1) << 3);    // 0..15
    const int rowg = (lane >> 3) | ((wid >> 1) << 2);  // 0..7
    const int brow = blockIdx.y * BMH;
    const int bcol = blockIdx.x * BNH;
    const int kz   = blockIdx.z;

    const int r = t >> 2;   // 0..31
    const int q = t & 3;    // 16B-quad
    const __half* Xsrc = Xh + (size_t)(brow + r) * IN_DIM + kz * KSEG;
    const __half* Wsrc = Wh + (size_t)(bcol + r) * IN_DIM + kz * KSEG + q * 8;

    const unsigned xs_base = (unsigned)__cvta_generic_to_shared(&xs[0][0]);
    const unsigned ws_base = (unsigned)__cvta_generic_to_shared(&ws[0][0][0]);
    const unsigned wd = ws_base + (unsigned)(r * PADK + q * 8) * 2;
    const unsigned WBUF   = (unsigned)(BNH * PADK) * 2;
    const unsigned WROW32 = (unsigned)(32 * PADK) * 2;

#define STAGE_W(c, buf) do {                                                 \
        const __half* wsp = Wsrc + (c) * BKH;                                \
        _Pragma("unroll")                                                    \
        for (int p = 0; p < 4; ++p) {                                        \
            CPA16(wd + (buf) * WBUF + p * WROW32,      wsp + (size_t)32 * p * IN_DIM); \
            CPA16(wd + (buf) * WBUF + p * WROW32 + 64, wsp + (size_t)32 * p * IN_DIM + 32); \
        }                                                                    \
        CPA_COMMIT();                                                        \
    } while (0)

    GRID_WAIT();   // prep's stores visible before first dependent read

    // stage ALL of X's K-segment once: 32 rows x 256B, quads q+4p
    {
        const unsigned xd = xs_base + (unsigned)(r * XPAD) * 2;
#pragma unroll
        for (int p = 0; p < 4; ++p)
            CPA16(xd + (unsigned)(q + 4 * p) * 16, Xsrc + (q + 4 * p) * 8);
    }
    STAGE_W(0, 0);   // X + W chunk 0 share commit group 0

    __half2 acc[4][8];
    const __half2 ninf = __floats2half2_rn(-60000.f, -60000.f);
#pragma unroll
    for (int i = 0; i < 4; ++i)
#pragma unroll
        for (int c = 0; c < 8; ++c)
            acc[i][c] = ninf;

#pragma unroll 1
    for (int c = 0; c < NCHH; ++c) {
        if (c + 1 < NCHH) { STAGE_W(c + 1, (c + 1) & 1); CPA_WAIT1(); }
        else              { CPA_WAIT0(); }
        __syncthreads();

        const int buf = c & 1;
        const __half* wb = &ws[buf][0][0];
        const __half* xb = &xs[0][0];

#pragma unroll 2
        for (int m = 0; m < 8; ++m) {
            const int xq = c * 8 + m;    // quad index within KSEG
            uint4 xv[4], wv[8];
#pragma unroll
            for (int i = 0; i < 4; ++i)
                xv[i] = *(const uint4*)(xb + (rowg + 8 * i) * XPAD + 8 * xq);
#pragma unroll
            for (int j = 0; j < 8; ++j)
                wv[j] = *(const uint4*)(wb + (colg + 16 * j) * PADK + 8 * m);

            const __half2* x2 = (const __half2*)xv;   // [i*4 + p]
            const __half2* w2 = (const __half2*)wv;   // [j*4 + p]
#pragma unroll
            for (int i = 0; i < 4; ++i)
#pragma unroll
                for (int j = 0; j < 8; ++j)
#pragma unroll
                    for (int p = 0; p < 4; ++p)
                        acc[i][j] = __hmax2(acc[i][j],
                                            __hadd2(x2[i * 4 + p], w2[j * 4 + p]));
        }

        if (c + 1 < NCHH) __syncthreads();   // protect W buf before restage
    }

    // epilogue: pair-reduce, write half partials
    __half* out = &g_parth[kz][0];
#pragma unroll
    for (int i = 0; i < 4; ++i)
#pragma unroll
        for (int j = 0; j < 8; ++j) {
            const __half2 a = acc[i][j];
            out[(size_t)(brow + rowg + 8 * i) * OUT_DIM + bcol + colg + 16 * j] =
                __hmax(__low2half(a), __high2half(a));
        }
    GRID_LAUNCH_DEP();
#undef STAGE_W
}

// ---------- combine: 8-way packed max + add back row shift ----------
__global__ __launch_bounds__(256)
void combine_max8(float* __restrict__ Y) {
    const int i = blockIdx.x * 256 + threadIdx.x;   // 8-half chunk index

    GRID_WAIT();   // all dependent reads (g_parth, Mrow) after wait

    const float M = Mrow[(i << 3) >> 10];           // 8 halves stay in one row
    uint4 v = ((const uint4*)g_parth[0])[i];
    __half2 m0 = ((const __half2*)&v)[0], m1 = ((const __half2*)&v)[1];
    __half2 m2 = ((const __half2*)&v)[2], m3 = ((const __half2*)&v)[3];
#pragma unroll
    for (int s = 1; s < SPLITK; ++s) {
        uint4 u = ((const uint4*)g_parth[s])[i];
        m0 = __hmax2(m0, ((const __half2*)&u)[0]);
        m1 = __hmax2(m1, ((const __half2*)&u)[1]);
        m2 = __hmax2(m2, ((const __half2*)&u)[2]);
        m3 = __hmax2(m3, ((const __half2*)&u)[3]);
    }
    float4* Yo = (float4*)(Y + ((size_t)i << 3));
    float2 f0 = __half22float2(m0), f1 = __half22float2(m1);
    float2 f2 = __half22float2(m2), f3 = __half22float2(m3);
    Yo[0] = make_float4(f0.x + M, f0.y + M, f1.x + M, f1.y + M);
    Yo[1] = make_float4(f2.x + M, f2.y + M, f3.x + M, f3.y + M);
}

extern "C" void kernel_launch(void* const* d_in, const int* in_sizes, int n_in,
                              void* d_out, int out_size) {
    const float* X = (const float*)d_in[0];   // [512, 1024]
    const float* W = (const float*)d_in[1];   // [1024, 1024]
    float* Y = (float*)d_out;                 // [512, 1024]
    (void)in_sizes; (void)n_in; (void)out_size;

    prep_xw<<<XPREP_BLOCKS + WPREP_BLOCKS, 256>>>(X, W);   // 320 blocks

    // main: PDL-dependent on prep
    {
        cudaLaunchConfig_t cfg = {};
        cfg.gridDim  = dim3(OUT_DIM / BNH, B_DIM / BMH, SPLITK);  // (8,16,8)
        cfg.blockDim = dim3(NT, 1, 1);
        cfg.dynamicSmemBytes = 0;
        cfg.stream = 0;
        cudaLaunchAttribute attr[1];
        attr[0].id = cudaLaunchAttributeProgrammaticStreamSerialization;
        attr[0].val.programmaticStreamSerializationAllowed = 1;
        cfg.attrs = attr;
        cfg.numAttrs = 1;
        cudaLaunchKernelEx(&cfg, tropical_h);
    }

    // combine: PDL-dependent on main
    {
        cudaLaunchConfig_t cfg = {};
        cfg.gridDim  = dim3(B_DIM * OUT_DIM / 8 / 256, 1, 1);     // 256 blocks
        cfg.blockDim = dim3(256, 1, 1);
        cfg.dynamicSmemBytes = 0;
        cfg.stream = 0;
        cudaLaunchAttribute attr[1];
        attr[0].id = cudaLaunchAttributeProgrammaticStreamSerialization;
        attr[0].val.programmaticStreamSerializationAllowed = 1;
        cfg.attrs = attr;
        cfg.numAttrs = 1;
        cudaLaunchKernelEx(&cfg, combine_max8, Y);
    }
}